// round 3
// baseline (speedup 1.0000x reference)
#include <cuda_runtime.h>
#include <math.h>

#define WIDTH   128
#define HEIGHT  128
#define NPIX    (WIDTH * HEIGHT)
#define NEARP   0.1f
#define FARP    10.0f
#define EPSV    1e-8f

#define TILE_W  32
#define TILE_H  8
#define TILES_X (WIDTH / TILE_W)            // 4
#define NTILES  ((WIDTH/TILE_W)*(HEIGHT/TILE_H)) // 64
#define CHUNK   64
#define MAXCHUNKS 64
#define SMAX_V  1024

// --------- scratch (device global; no allocation allowed) -------------------
__device__ unsigned long long g_part[MAXCHUNKS][NPIX];

__device__ __forceinline__ float f_nan() { return __int_as_float(0x7fc00000); }
__device__ __forceinline__ float f_inf() { return __int_as_float(0x7f800000); }

// --------- camera matrix (view @ proj), single thread -----------------------
__device__ void compute_matrix(const float* camf, const float* camc,
                               const float* camt, const float* camrt,
                               float* M /* 16, row-major */)
{
    // perspective
    float f   = 0.5f * (camf[0] + camf[1]);
    float ccx = camc[0], ccy = camc[1];
    float nf  = NEARP / f;
    float right = ((float)WIDTH - (ccx + 0.5f)) * nf;
    float left  = -(ccx + 0.5f) * nf;
    float top   = (ccy + 0.5f) * nf;
    float bot   = -((float)HEIGHT - ccy + 0.5f) * nf;
    float m[4][4];
    #pragma unroll
    for (int i = 0; i < 4; i++)
        #pragma unroll
        for (int j = 0; j < 4; j++) m[i][j] = 0.0f;
    m[0][0] = 2.0f * NEARP / (right - left); m[0][2] = (right + left) / (right - left);
    m[1][1] = 2.0f * NEARP / (top - bot);    m[1][2] = (top + bot) / (top - bot);
    m[2][2] = -(FARP + NEARP) / (FARP - NEARP);
    m[2][3] = -2.0f * FARP * NEARP / (FARP - NEARP);
    m[3][2] = -1.0f;
    float P[4][4];
    #pragma unroll
    for (int i = 0; i < 4; i++)
        #pragma unroll
        for (int j = 0; j < 4; j++) P[i][j] = m[j][i];

    // rodrigues
    float rx = camrt[0], ry = camrt[1], rz = camrt[2];
    float th = sqrtf(rx * rx + ry * ry + rz * rz + 1e-12f);
    float kx = rx / th, ky = ry / th, kz = rz / th;
    float s  = sinf(th);
    float cc = 1.0f - cosf(th);
    float K[3][3] = {{0.f, -kz, ky}, {kz, 0.f, -kx}, {-ky, kx, 0.f}};
    float K2[3][3];
    #pragma unroll
    for (int i = 0; i < 3; i++)
        #pragma unroll
        for (int j = 0; j < 3; j++) {
            float acc = 0.f;
            #pragma unroll
            for (int k = 0; k < 3; k++) acc += K[i][k] * K[k][j];
            K2[i][j] = acc;
        }
    float R[3][3];
    #pragma unroll
    for (int i = 0; i < 3; i++)
        #pragma unroll
        for (int j = 0; j < 3; j++)
            R[i][j] = (i == j ? 1.0f : 0.0f) + s * K[i][j] + cc * K2[i][j];

    // view = Mr @ Mt
    float Vw[4][4];
    #pragma unroll
    for (int i = 0; i < 4; i++)
        #pragma unroll
        for (int j = 0; j < 4; j++) Vw[i][j] = 0.0f;
    #pragma unroll
    for (int i = 0; i < 3; i++)
        #pragma unroll
        for (int j = 0; j < 3; j++) Vw[i][j] = R[j][i];
    Vw[3][0] = camt[0]; Vw[3][1] = camt[1]; Vw[3][2] = camt[2];
    Vw[3][3] = 1.0f;

    // M = view @ proj
    #pragma unroll
    for (int i = 0; i < 4; i++)
        #pragma unroll
        for (int j = 0; j < 4; j++) {
            float acc = 0.f;
            #pragma unroll
            for (int k = 0; k < 4; k++) acc += Vw[i][k] * P[k][j];
            M[i * 4 + j] = acc;
        }
}

// --------- vertex transform (shared by both kernels, identical fp ops) ------
__device__ __forceinline__ void transform_vertex(const float* __restrict__ v, int i,
                                                 const float* __restrict__ M,
                                                 float& sx, float& sy, float& nz,
                                                 float& iw, bool& valid)
{
    float x = v[3 * i], y = v[3 * i + 1], z = v[3 * i + 2];
    float c0 = x * M[0]  + y * M[4]  + z * M[8]  + M[12];
    float c1 = x * M[1]  + y * M[5]  + z * M[9]  + M[13];
    float c2 = x * M[2]  + y * M[6]  + z * M[10] + M[14];
    float c3 = x * M[3]  + y * M[7]  + z * M[11] + M[15];
    valid = (c3 > EPSV);
    float ws = valid ? c3 : 1.0f;
    float nx = c0 / ws, ny = c1 / ws;
    nz = c2 / ws;
    sx = (nx * 0.5f + 0.5f) * (float)WIDTH;
    sy = (0.5f - ny * 0.5f) * (float)HEIGHT;
    iw = 1.0f / ws;
}

// --------- kernel 1: fused setup + tiled chunked raster ---------------------
__global__ void raster_kernel(const float* __restrict__ v,
                              const int* __restrict__ f,
                              const float* __restrict__ camf,
                              const float* __restrict__ camc,
                              const float* __restrict__ camt,
                              const float* __restrict__ camrt,
                              int V, int F)
{
    __shared__ float  sM[16];
    __shared__ float  svx[SMAX_V], svy[SMAX_V], svz[SMAX_V];
    __shared__ float4 s0[CHUNK], s1[CHUNK], s2[CHUNK], s3[CHUNK], sbb[CHUNK];

    int tid = threadIdx.x;
    if (tid == 0) compute_matrix(camf, camc, camt, camrt, sM);
    __syncthreads();

    // vertices -> smem
    for (int i = tid; i < V; i += blockDim.x) {
        float sx, sy, nz, iw; bool valid;
        transform_vertex(v, i, sM, sx, sy, nz, iw, valid);
        svx[i] = sx; svy[i] = sy;
        svz[i] = valid ? nz : f_nan();
    }
    __syncthreads();

    // this block's triangle chunk -> smem records
    int chunk = blockIdx.y;
    int tbase = chunk * CHUNK;
    int nt = F - tbase; if (nt > CHUNK) nt = CHUNK;

    if (tid < nt) {
        int t = tbase + tid;
        int i0 = f[3 * t], i1 = f[3 * t + 1], i2 = f[3 * t + 2];
        float ax = svx[i0], ay = svy[i0];
        float bx = svx[i1], by = svy[i1];
        float cx = svx[i2], cy = svy[i2];
        float e0x = cx - bx, e0y = cy - by;
        float e1x = ax - cx, e1y = ay - cy;
        float e2x = bx - ax, e2y = by - ay;
        float area = e2x * (cy - ay) - e2y * (cx - ax);
        bool areaok = fabsf(area) > EPSV;
        float inva = 1.0f / (areaok ? area : 1.0f);
        float za = svz[i0], zb = svz[i1], zc = svz[i2];
        if (!areaok) za = f_nan();
        s0[tid] = make_float4(e0x, e0y, bx, by);
        s1[tid] = make_float4(e1x, e1y, cx, cy);
        s2[tid] = make_float4(e2x, e2y, ax, ay);
        s3[tid] = make_float4(za, zb, zc, inva);
        float xmn = fminf(ax, fminf(bx, cx));
        float xmx = fmaxf(ax, fmaxf(bx, cx));
        float ymn = fminf(ay, fminf(by, cy));
        float ymx = fmaxf(ay, fmaxf(by, cy));
        sbb[tid] = make_float4(xmn, xmx, ymn, ymx);
    }
    __syncthreads();

    // raster
    int tile = blockIdx.x;
    int tx = tile % TILES_X, ty = tile / TILES_X;
    int lx = tid % TILE_W,   ly = tid / TILE_W;
    int pxi = tx * TILE_W + lx;
    int pyi = ty * TILE_H + ly;
    float px = (float)pxi + 0.5f;
    float py = (float)pyi + 0.5f;
    float tileL = (float)(tx * TILE_W);
    float tileR = tileL + (float)TILE_W;
    float tileT = (float)(ty * TILE_H);
    float tileB = tileT + (float)TILE_H;

    float bestz = f_inf();
    int   besti = tbase;

    for (int i = 0; i < nt; i++) {
        float4 bb = sbb[i];  // xmin, xmax, ymin, ymax (uniform across block)
        if (bb.y < tileL || bb.x > tileR || bb.w < tileT || bb.z > tileB) continue;
        float4 q0 = s0[i];
        float4 q1 = s1[i];
        float4 q2 = s2[i];
        float4 q3 = s3[i];
        float w0 = q0.x * (py - q0.w) - q0.y * (px - q0.z); // E(b,c)
        float w1 = q1.x * (py - q1.w) - q1.y * (px - q1.z); // E(c,a)
        float w2 = q2.x * (py - q2.w) - q2.y * (px - q2.z); // E(a,b)
        float b0 = w0 * q3.w;
        float b1 = w1 * q3.w;
        float b2 = w2 * q3.w;
        float z  = b0 * q3.x + b1 * q3.y + b2 * q3.z;       // NaN if invalid
        bool inside = (b0 >= 0.0f) & (b1 >= 0.0f) & (b2 >= 0.0f) &
                      (z >= -1.0f) & (z <= 1.0f);
        if (inside && (z < bestz)) { bestz = z; besti = tbase + i; }
    }

    unsigned int d = __float_as_uint(bestz);
    d = (d & 0x80000000u) ? ~d : (d | 0x80000000u);
    g_part[chunk][pyi * WIDTH + pxi] =
        ((unsigned long long)d << 32) | (unsigned int)besti;
}

// --------- kernel 2: reduce + shade (recompute winning tri) -----------------
__global__ void shade_kernel(const float* __restrict__ v,
                             const float* __restrict__ vc,
                             const int* __restrict__ f,
                             const float* __restrict__ bg,
                             const float* __restrict__ camf,
                             const float* __restrict__ camc,
                             const float* __restrict__ camt,
                             const float* __restrict__ camrt,
                             float* __restrict__ out,
                             int nchunks)
{
    __shared__ float sM[16];
    if (threadIdx.x == 0) compute_matrix(camf, camc, camt, camrt, sM);
    __syncthreads();

    int p = blockIdx.x * blockDim.x + threadIdx.x;
    if (p >= NPIX) return;

    unsigned long long best = g_part[0][p];
    for (int c = 1; c < nchunks; c++) {
        unsigned long long k = g_part[c][p];
        if (k < best) best = k;
    }
    unsigned int d = (unsigned int)(best >> 32);
    const unsigned int one_enc = __float_as_uint(1.0f) | 0x80000000u;

    float r, g, bl;
    if (d <= one_enc) {
        int t = (int)(unsigned int)(best & 0xffffffffu);
        int i0 = f[3 * t], i1 = f[3 * t + 1], i2 = f[3 * t + 2];
        float ax, ay, bx, by, cx, cy, z0, z1, z2, iw0, iw1, iw2; bool vb;
        transform_vertex(v, i0, sM, ax, ay, z0, iw0, vb);
        transform_vertex(v, i1, sM, bx, by, z1, iw1, vb);
        transform_vertex(v, i2, sM, cx, cy, z2, iw2, vb);
        float px = (float)(p % WIDTH) + 0.5f;
        float py = (float)(p / WIDTH) + 0.5f;
        float w0 = (cx - bx) * (py - by) - (cy - by) * (px - bx);
        float w1 = (ax - cx) * (py - cy) - (ay - cy) * (px - cx);
        float w2 = (bx - ax) * (py - ay) - (by - ay) * (px - ax);
        float area = (bx - ax) * (cy - ay) - (by - ay) * (cx - ax);
        bool areaok = fabsf(area) > EPSV;
        float inva = 1.0f / (areaok ? area : 1.0f);
        float b0 = w0 * inva;
        float b1 = w1 * inva;
        float b2 = w2 * inva;
        float g0 = b0 * iw0, g1 = b1 * iw1, g2 = b2 * iw2;
        float den = g0 + g1 + g2;
        den = (fabsf(den) > EPSV) ? den : 1.0f;
        r  = (g0 * vc[3 * i0 + 0] + g1 * vc[3 * i1 + 0] + g2 * vc[3 * i2 + 0]) / den;
        g  = (g0 * vc[3 * i0 + 1] + g1 * vc[3 * i1 + 1] + g2 * vc[3 * i2 + 1]) / den;
        bl = (g0 * vc[3 * i0 + 2] + g1 * vc[3 * i1 + 2] + g2 * vc[3 * i2 + 2]) / den;
    } else {
        r = bg[0]; g = bg[1]; bl = bg[2];
    }
    out[3 * p + 0] = r;
    out[3 * p + 1] = g;
    out[3 * p + 2] = bl;
}

// --------- launch -----------------------------------------------------------
extern "C" void kernel_launch(void* const* d_in, const int* in_sizes, int n_in,
                              void* d_out, int out_size)
{
    const float* v     = (const float*)d_in[0];
    const float* vc    = (const float*)d_in[1];
    const int*   f     = (const int*)  d_in[2];
    const float* bg    = (const float*)d_in[3];
    const float* camf  = (const float*)d_in[4];
    const float* camc  = (const float*)d_in[5];
    const float* camt  = (const float*)d_in[6];
    const float* camrt = (const float*)d_in[7];

    int B = out_size / (NPIX * 3);
    int V = in_sizes[1] / 3;
    int F = in_sizes[2] / 3;
    int nchunks = (F + CHUNK - 1) / CHUNK;
    if (nchunks > MAXCHUNKS) nchunks = MAXCHUNKS;

    for (int b = 0; b < B; b++) {
        const float* vb = v + (size_t)b * V * 3;
        dim3 rgrid(NTILES, nchunks);
        raster_kernel<<<rgrid, 256>>>(vb, f, camf, camc, camt, camrt, V, F);
        shade_kernel<<<NPIX / 256, 256>>>(vb, vc, f, bg, camf, camc, camt, camrt,
                                          (float*)d_out + (size_t)b * NPIX * 3,
                                          nchunks);
    }
}

// round 4
// speedup vs baseline: 1.2206x; 1.2206x over previous
#include <cuda_runtime.h>
#include <math.h>

#define WIDTH   128
#define HEIGHT  128
#define NPIX    (WIDTH * HEIGHT)
#define NEARP   0.1f
#define FARP    10.0f
#define EPSV    1e-8f

#define TILE_W  32
#define TILE_H  8
#define TILES_X (WIDTH / TILE_W)                  // 4
#define NTILES  ((WIDTH/TILE_W)*(HEIGHT/TILE_H))  // 64
#define CHUNK   256
#define SMAX_V  1024

// --------- scratch (device globals; zero-initialized at module load) --------
__device__ unsigned long long g_best[NPIX];   // stores ~key; 0 == empty
__device__ float4 g_vdata[SMAX_V];            // x, y, z(NaN if invalid), 1/w

__device__ __forceinline__ float f_nan() { return __int_as_float(0x7fc00000); }

// --------- camera matrix (view @ proj) --------------------------------------
__device__ void compute_matrix(const float* camf, const float* camc,
                               const float* camt, const float* camrt,
                               float* M /* 16, row-major */)
{
    float f   = 0.5f * (camf[0] + camf[1]);
    float ccx = camc[0], ccy = camc[1];
    float nf  = NEARP / f;
    float right = ((float)WIDTH - (ccx + 0.5f)) * nf;
    float left  = -(ccx + 0.5f) * nf;
    float top   = (ccy + 0.5f) * nf;
    float bot   = -((float)HEIGHT - ccy + 0.5f) * nf;
    float m[4][4];
    #pragma unroll
    for (int i = 0; i < 4; i++)
        #pragma unroll
        for (int j = 0; j < 4; j++) m[i][j] = 0.0f;
    m[0][0] = 2.0f * NEARP / (right - left); m[0][2] = (right + left) / (right - left);
    m[1][1] = 2.0f * NEARP / (top - bot);    m[1][2] = (top + bot) / (top - bot);
    m[2][2] = -(FARP + NEARP) / (FARP - NEARP);
    m[2][3] = -2.0f * FARP * NEARP / (FARP - NEARP);
    m[3][2] = -1.0f;
    float P[4][4];
    #pragma unroll
    for (int i = 0; i < 4; i++)
        #pragma unroll
        for (int j = 0; j < 4; j++) P[i][j] = m[j][i];

    float rx = camrt[0], ry = camrt[1], rz = camrt[2];
    float th = sqrtf(rx * rx + ry * ry + rz * rz + 1e-12f);
    float kx = rx / th, ky = ry / th, kz = rz / th;
    float s  = sinf(th);
    float cc = 1.0f - cosf(th);
    float K[3][3] = {{0.f, -kz, ky}, {kz, 0.f, -kx}, {-ky, kx, 0.f}};
    float K2[3][3];
    #pragma unroll
    for (int i = 0; i < 3; i++)
        #pragma unroll
        for (int j = 0; j < 3; j++) {
            float acc = 0.f;
            #pragma unroll
            for (int k = 0; k < 3; k++) acc += K[i][k] * K[k][j];
            K2[i][j] = acc;
        }
    float R[3][3];
    #pragma unroll
    for (int i = 0; i < 3; i++)
        #pragma unroll
        for (int j = 0; j < 3; j++)
            R[i][j] = (i == j ? 1.0f : 0.0f) + s * K[i][j] + cc * K2[i][j];

    float Vw[4][4];
    #pragma unroll
    for (int i = 0; i < 4; i++)
        #pragma unroll
        for (int j = 0; j < 4; j++) Vw[i][j] = 0.0f;
    #pragma unroll
    for (int i = 0; i < 3; i++)
        #pragma unroll
        for (int j = 0; j < 3; j++) Vw[i][j] = R[j][i];
    Vw[3][0] = camt[0]; Vw[3][1] = camt[1]; Vw[3][2] = camt[2];
    Vw[3][3] = 1.0f;

    #pragma unroll
    for (int i = 0; i < 4; i++)
        #pragma unroll
        for (int j = 0; j < 4; j++) {
            float acc = 0.f;
            #pragma unroll
            for (int k = 0; k < 4; k++) acc += Vw[i][k] * P[k][j];
            M[i * 4 + j] = acc;
        }
}

__device__ __forceinline__ float4 transform_vertex(const float* __restrict__ v,
                                                   int i, const float* __restrict__ M)
{
    float x = v[3 * i], y = v[3 * i + 1], z = v[3 * i + 2];
    float c0 = x * M[0] + y * M[4] + z * M[8]  + M[12];
    float c1 = x * M[1] + y * M[5] + z * M[9]  + M[13];
    float c2 = x * M[2] + y * M[6] + z * M[10] + M[14];
    float c3 = x * M[3] + y * M[7] + z * M[11] + M[15];
    bool valid = (c3 > EPSV);
    float ws = valid ? c3 : 1.0f;
    float nx = c0 / ws, ny = c1 / ws, nz = c2 / ws;
    float4 r;
    r.x = (nx * 0.5f + 0.5f) * (float)WIDTH;
    r.y = (0.5f - ny * 0.5f) * (float)HEIGHT;
    r.z = valid ? nz : f_nan();
    r.w = 1.0f / ws;
    return r;
}

// --------- kernel 1: fused setup + tiled chunked raster + atomic z ----------
__global__ void __launch_bounds__(256)
raster_kernel(const float* __restrict__ v,
              const int* __restrict__ f,
              const float* __restrict__ camf,
              const float* __restrict__ camc,
              const float* __restrict__ camt,
              const float* __restrict__ camrt,
              int V, int F)
{
    __shared__ float  sM[16];
    __shared__ float4 svd[SMAX_V];
    __shared__ float4 s0[CHUNK], s1[CHUNK], s2[CHUNK], s3[CHUNK], sbb[CHUNK];

    int tid = threadIdx.x;
    if (tid == 0) compute_matrix(camf, camc, camt, camrt, sM);
    __syncthreads();

    for (int i = tid; i < V; i += blockDim.x)
        svd[i] = transform_vertex(v, i, sM);
    __syncthreads();

    // publish transformed vertices once for the shade kernel
    if (blockIdx.x == 0 && blockIdx.y == 0)
        for (int i = tid; i < V; i += blockDim.x)
            g_vdata[i] = svd[i];

    // this block's triangle chunk -> smem records
    int chunk = blockIdx.y;
    int tbase = chunk * CHUNK;
    int nt = F - tbase; if (nt > CHUNK) nt = CHUNK;

    if (tid < nt) {
        int t = tbase + tid;
        int i0 = f[3 * t], i1 = f[3 * t + 1], i2 = f[3 * t + 2];
        float4 A = svd[i0], Bv = svd[i1], C = svd[i2];
        float ax = A.x, ay = A.y, bx = Bv.x, by = Bv.y, cx = C.x, cy = C.y;
        float e0x = cx - bx, e0y = cy - by;
        float e1x = ax - cx, e1y = ay - cy;
        float e2x = bx - ax, e2y = by - ay;
        float area = e2x * (cy - ay) - e2y * (cx - ax);
        bool areaok = fabsf(area) > EPSV;
        float inva = 1.0f / (areaok ? area : 1.0f);
        float za = A.z, zb = Bv.z, zc = C.z;      // NaN if vert invalid
        if (!areaok) za = f_nan();
        s0[tid] = make_float4(e0x, e0y, bx, by);
        s1[tid] = make_float4(e1x, e1y, cx, cy);
        s2[tid] = make_float4(e2x, e2y, ax, ay);
        s3[tid] = make_float4(za, zb, zc, inva);
        float xmn = fminf(ax, fminf(bx, cx));
        float xmx = fmaxf(ax, fmaxf(bx, cx));
        float ymn = fminf(ay, fminf(by, cy));
        float ymx = fmaxf(ay, fmaxf(by, cy));
        sbb[tid] = make_float4(xmn, xmx, ymn, ymx);
    }
    __syncthreads();

    // raster this tile against the chunk
    int tile = blockIdx.x;
    int tx = tile % TILES_X, ty = tile / TILES_X;
    int lx = tid % TILE_W,   ly = tid / TILE_W;
    int pxi = tx * TILE_W + lx;
    int pyi = ty * TILE_H + ly;
    float px = (float)pxi + 0.5f;
    float py = (float)pyi + 0.5f;
    float tileL = (float)(tx * TILE_W);
    float tileR = tileL + (float)TILE_W;
    float tileT = (float)(ty * TILE_H);
    float tileB = tileT + (float)TILE_H;

    float bestz = 0.0f;
    int   besti = -1;

    #pragma unroll 4
    for (int i = 0; i < nt; i++) {
        float4 bb = sbb[i];
        if (bb.y < tileL || bb.x > tileR || bb.w < tileT || bb.z > tileB) continue;
        float4 q0 = s0[i];
        float4 q1 = s1[i];
        float4 q2 = s2[i];
        float4 q3 = s3[i];
        float w0 = q0.x * (py - q0.w) - q0.y * (px - q0.z); // E(b,c)
        float w1 = q1.x * (py - q1.w) - q1.y * (px - q1.z); // E(c,a)
        float w2 = q2.x * (py - q2.w) - q2.y * (px - q2.z); // E(a,b)
        float b0 = w0 * q3.w;
        float b1 = w1 * q3.w;
        float b2 = w2 * q3.w;
        float z  = b0 * q3.x + b1 * q3.y + b2 * q3.z;       // NaN if invalid
        bool inside = (b0 >= 0.0f) & (b1 >= 0.0f) & (b2 >= 0.0f) &
                      (z >= -1.0f) & (z <= 1.0f);
        if (inside && (besti < 0 || z < bestz)) { bestz = z; besti = tbase + i; }
    }

    if (besti >= 0) {
        unsigned int d = __float_as_uint(bestz);
        d = (d & 0x80000000u) ? ~d : (d | 0x80000000u);
        unsigned long long key =
            ((unsigned long long)d << 32) | (unsigned int)besti;
        atomicMax(&g_best[pyi * WIDTH + pxi], ~key);   // max(~key) == ~min(key); 0 == empty
    }
}

// --------- kernel 2: shade (1 key load + precomputed vertex data) -----------
__global__ void __launch_bounds__(256)
shade_kernel(const float* __restrict__ vc,
             const int* __restrict__ f,
             const float* __restrict__ bg,
             float* __restrict__ out)
{
    int p = blockIdx.x * blockDim.x + threadIdx.x;
    if (p >= NPIX) return;

    unsigned long long m = g_best[p];
    g_best[p] = 0ull;                 // self-reset for next graph replay

    float r, g, bl;
    if (m != 0ull) {
        unsigned long long key = ~m;
        int t = (int)(unsigned int)(key & 0xffffffffu);
        int i0 = f[3 * t], i1 = f[3 * t + 1], i2 = f[3 * t + 2];
        float4 A = g_vdata[i0], Bv = g_vdata[i1], C = g_vdata[i2];
        float ax = A.x, ay = A.y, bx = Bv.x, by = Bv.y, cx = C.x, cy = C.y;
        float px = (float)(p % WIDTH) + 0.5f;
        float py = (float)(p / WIDTH) + 0.5f;
        float w0 = (cx - bx) * (py - by) - (cy - by) * (px - bx);
        float w1 = (ax - cx) * (py - cy) - (ay - cy) * (px - cx);
        float w2 = (bx - ax) * (py - ay) - (by - ay) * (px - ax);
        float area = (bx - ax) * (cy - ay) - (by - ay) * (cx - ax);
        bool areaok = fabsf(area) > EPSV;
        float inva = 1.0f / (areaok ? area : 1.0f);
        float b0 = w0 * inva;
        float b1 = w1 * inva;
        float b2 = w2 * inva;
        float g0 = b0 * A.w, g1 = b1 * Bv.w, g2 = b2 * C.w;
        float den = g0 + g1 + g2;
        den = (fabsf(den) > EPSV) ? den : 1.0f;
        r  = (g0 * vc[3 * i0 + 0] + g1 * vc[3 * i1 + 0] + g2 * vc[3 * i2 + 0]) / den;
        g  = (g0 * vc[3 * i0 + 1] + g1 * vc[3 * i1 + 1] + g2 * vc[3 * i2 + 1]) / den;
        bl = (g0 * vc[3 * i0 + 2] + g1 * vc[3 * i1 + 2] + g2 * vc[3 * i2 + 2]) / den;
    } else {
        r = bg[0]; g = bg[1]; bl = bg[2];
    }
    out[3 * p + 0] = r;
    out[3 * p + 1] = g;
    out[3 * p + 2] = bl;
}

// --------- launch -----------------------------------------------------------
extern "C" void kernel_launch(void* const* d_in, const int* in_sizes, int n_in,
                              void* d_out, int out_size)
{
    const float* v     = (const float*)d_in[0];
    const float* vc    = (const float*)d_in[1];
    const int*   f     = (const int*)  d_in[2];
    const float* bg    = (const float*)d_in[3];
    const float* camf  = (const float*)d_in[4];
    const float* camc  = (const float*)d_in[5];
    const float* camt  = (const float*)d_in[6];
    const float* camrt = (const float*)d_in[7];

    int B = out_size / (NPIX * 3);
    int V = in_sizes[1] / 3;
    int F = in_sizes[2] / 3;
    int nchunks = (F + CHUNK - 1) / CHUNK;

    for (int b = 0; b < B; b++) {
        const float* vb = v + (size_t)b * V * 3;
        dim3 rgrid(NTILES, nchunks);
        raster_kernel<<<rgrid, 256>>>(vb, f, camf, camc, camt, camrt, V, F);
        shade_kernel<<<NPIX / 256, 256>>>(vc, f, bg,
                                          (float*)d_out + (size_t)b * NPIX * 3);
    }
}

// round 5
// speedup vs baseline: 1.4196x; 1.1630x over previous
#include <cuda_runtime.h>
#include <math.h>

#define WIDTH   128
#define HEIGHT  128
#define NPIX    (WIDTH * HEIGHT)
#define NEARP   0.1f
#define FARP    10.0f
#define EPSV    1e-8f

#define TILE_W   16
#define TILE_H   8
#define TILES_X  (WIDTH / TILE_W)                   // 8
#define NBLOCKS  ((WIDTH/TILE_W)*(HEIGHT/TILE_H))   // 128
#define NTHREADS 256
#define PIXPB    (TILE_W * TILE_H)                  // 128
#define VCAP     1024
#define FCAP     1024

struct Smem {
    float4 svd[VCAP];                 // x, y, z(NaN if invalid), 1/w
    float4 s0[FCAP];                  // e0x, e0y, bx, by
    float4 s1[FCAP];                  // e1x, e1y, cx, cy
    float4 s2[FCAP];                  // e2x, e2y, ax, ay
    float4 s3[FCAP];                  // za, zb, zc, inva
    int    slist[FCAP];
    unsigned long long mergebuf[PIXPB];
    float  sM[16];
    int    wtot[8];
    int    wbase[8];
    int    slen;
};

__device__ __forceinline__ float f_nan() { return __int_as_float(0x7fc00000); }

// --------- camera matrix (view @ proj) --------------------------------------
__device__ void compute_matrix(const float* camf, const float* camc,
                               const float* camt, const float* camrt,
                               float* M)
{
    float f   = 0.5f * (camf[0] + camf[1]);
    float ccx = camc[0], ccy = camc[1];
    float nf  = NEARP / f;
    float right = ((float)WIDTH - (ccx + 0.5f)) * nf;
    float left  = -(ccx + 0.5f) * nf;
    float top   = (ccy + 0.5f) * nf;
    float bot   = -((float)HEIGHT - ccy + 0.5f) * nf;
    float m[4][4];
    #pragma unroll
    for (int i = 0; i < 4; i++)
        #pragma unroll
        for (int j = 0; j < 4; j++) m[i][j] = 0.0f;
    m[0][0] = 2.0f * NEARP / (right - left); m[0][2] = (right + left) / (right - left);
    m[1][1] = 2.0f * NEARP / (top - bot);    m[1][2] = (top + bot) / (top - bot);
    m[2][2] = -(FARP + NEARP) / (FARP - NEARP);
    m[2][3] = -2.0f * FARP * NEARP / (FARP - NEARP);
    m[3][2] = -1.0f;
    float P[4][4];
    #pragma unroll
    for (int i = 0; i < 4; i++)
        #pragma unroll
        for (int j = 0; j < 4; j++) P[i][j] = m[j][i];

    float rx = camrt[0], ry = camrt[1], rz = camrt[2];
    float th = sqrtf(rx * rx + ry * ry + rz * rz + 1e-12f);
    float kx = rx / th, ky = ry / th, kz = rz / th;
    float s  = sinf(th);
    float cc = 1.0f - cosf(th);
    float K[3][3] = {{0.f, -kz, ky}, {kz, 0.f, -kx}, {-ky, kx, 0.f}};
    float K2[3][3];
    #pragma unroll
    for (int i = 0; i < 3; i++)
        #pragma unroll
        for (int j = 0; j < 3; j++) {
            float acc = 0.f;
            #pragma unroll
            for (int k = 0; k < 3; k++) acc += K[i][k] * K[k][j];
            K2[i][j] = acc;
        }
    float R[3][3];
    #pragma unroll
    for (int i = 0; i < 3; i++)
        #pragma unroll
        for (int j = 0; j < 3; j++)
            R[i][j] = (i == j ? 1.0f : 0.0f) + s * K[i][j] + cc * K2[i][j];

    float Vw[4][4];
    #pragma unroll
    for (int i = 0; i < 4; i++)
        #pragma unroll
        for (int j = 0; j < 4; j++) Vw[i][j] = 0.0f;
    #pragma unroll
    for (int i = 0; i < 3; i++)
        #pragma unroll
        for (int j = 0; j < 3; j++) Vw[i][j] = R[j][i];
    Vw[3][0] = camt[0]; Vw[3][1] = camt[1]; Vw[3][2] = camt[2];
    Vw[3][3] = 1.0f;

    #pragma unroll
    for (int i = 0; i < 4; i++)
        #pragma unroll
        for (int j = 0; j < 4; j++) {
            float acc = 0.f;
            #pragma unroll
            for (int k = 0; k < 4; k++) acc += Vw[i][k] * P[k][j];
            M[i * 4 + j] = acc;
        }
}

__device__ __forceinline__ float4 transform_vertex(const float* __restrict__ v,
                                                   int i, const float* __restrict__ M)
{
    float x = v[3 * i], y = v[3 * i + 1], z = v[3 * i + 2];
    float c0 = x * M[0] + y * M[4] + z * M[8]  + M[12];
    float c1 = x * M[1] + y * M[5] + z * M[9]  + M[13];
    float c2 = x * M[2] + y * M[6] + z * M[10] + M[14];
    float c3 = x * M[3] + y * M[7] + z * M[11] + M[15];
    bool valid = (c3 > EPSV);
    float ws = valid ? c3 : 1.0f;
    float nx = c0 / ws, ny = c1 / ws, nz = c2 / ws;
    float4 r;
    r.x = (nx * 0.5f + 0.5f) * (float)WIDTH;
    r.y = (0.5f - ny * 0.5f) * (float)HEIGHT;
    r.z = valid ? nz : f_nan();
    r.w = 1.0f / ws;
    return r;
}

// --------- the whole renderer in one kernel ---------------------------------
__global__ void __launch_bounds__(NTHREADS, 1)
render_kernel(const float* __restrict__ v,
              const float* __restrict__ vc,
              const int* __restrict__ f,
              const float* __restrict__ bg,
              const float* __restrict__ camf,
              const float* __restrict__ camc,
              const float* __restrict__ camt,
              const float* __restrict__ camrt,
              float* __restrict__ out,
              int V, int F)
{
    extern __shared__ char raw[];
    Smem* sm = (Smem*)raw;

    int tid  = threadIdx.x;
    int lane = tid & 31;
    int wid  = tid >> 5;

    if (tid == 0) compute_matrix(camf, camc, camt, camrt, sm->sM);
    __syncthreads();

    // ---- phase 1: vertices -> smem
    for (int i = tid; i < V; i += NTHREADS)
        sm->svd[i] = transform_vertex(v, i, sm->sM);
    __syncthreads();

    // ---- tile geometry
    int tile = blockIdx.x;
    int tx0 = (tile % TILES_X) * TILE_W;
    int ty0 = (tile / TILES_X) * TILE_H;
    float tileL = (float)tx0,            tileR = (float)(tx0 + TILE_W);
    float tileT = (float)ty0,            tileB = (float)(ty0 + TILE_H);

    // ---- phase 2: ordered bbox compaction (thread t owns tris [4t, 4t+4))
    int tbase = tid * 4;
    unsigned passbits = 0;
    int cnt = 0;
    #pragma unroll
    for (int j = 0; j < 4; j++) {
        int t = tbase + j;
        if (t < F) {
            int i0 = f[3 * t], i1 = f[3 * t + 1], i2 = f[3 * t + 2];
            float4 A = sm->svd[i0], B = sm->svd[i1], C = sm->svd[i2];
            float xmn = fminf(A.x, fminf(B.x, C.x));
            float xmx = fmaxf(A.x, fmaxf(B.x, C.x));
            float ymn = fminf(A.y, fminf(B.y, C.y));
            float ymx = fmaxf(A.y, fmaxf(B.y, C.y));
            // keep if bbox overlaps tile rect, OR any comparison involves NaN
            // (NaN coords: all four compares false -> reject==false -> kept; harmless)
            bool reject = (xmx < tileL) | (xmn > tileR) | (ymx < tileT) | (ymn > tileB);
            if (!reject) { passbits |= (1u << j); cnt++; }
        }
    }
    // block exclusive scan of cnt (warp shuffle + warp totals)
    int x = cnt;
    #pragma unroll
    for (int o = 1; o < 32; o <<= 1) {
        int y = __shfl_up_sync(0xffffffffu, x, o);
        if (lane >= o) x += y;
    }
    if (lane == 31) sm->wtot[wid] = x;
    __syncthreads();
    if (tid == 0) {
        int s = 0;
        #pragma unroll
        for (int i = 0; i < 8; i++) { sm->wbase[i] = s; s += sm->wtot[i]; }
        sm->slen = s;
    }
    __syncthreads();
    int o = sm->wbase[wid] + x - cnt;   // exclusive offset, global order preserved
    #pragma unroll
    for (int j = 0; j < 4; j++)
        if (passbits & (1u << j)) sm->slist[o++] = tbase + j;
    __syncthreads();

    int listlen = sm->slen;

    // ---- phase 3: setup surviving triangles (same fp forms as before)
    for (int k = tid; k < listlen; k += NTHREADS) {
        int t = sm->slist[k];
        int i0 = f[3 * t], i1 = f[3 * t + 1], i2 = f[3 * t + 2];
        float4 A = sm->svd[i0], Bv = sm->svd[i1], C = sm->svd[i2];
        float ax = A.x, ay = A.y, bx = Bv.x, by = Bv.y, cx = C.x, cy = C.y;
        float e0x = cx - bx, e0y = cy - by;
        float e1x = ax - cx, e1y = ay - cy;
        float e2x = bx - ax, e2y = by - ay;
        float area = e2x * (cy - ay) - e2y * (cx - ax);
        bool areaok = fabsf(area) > EPSV;
        float inva = 1.0f / (areaok ? area : 1.0f);
        float za = A.z, zb = Bv.z, zc = C.z;   // NaN if vert invalid
        if (!areaok) za = f_nan();
        sm->s0[k] = make_float4(e0x, e0y, bx, by);
        sm->s1[k] = make_float4(e1x, e1y, cx, cy);
        sm->s2[k] = make_float4(e2x, e2y, ax, ay);
        sm->s3[k] = make_float4(za, zb, zc, inva);
    }
    __syncthreads();

    // ---- phase 4: raster. tid&127 = pixel, tid>>7 = list half.
    int pix  = tid & (PIXPB - 1);
    int half = tid >> 7;
    int pxi = tx0 + (pix % TILE_W);
    int pyi = ty0 + (pix / TILE_W);
    float px = (float)pxi + 0.5f;
    float py = (float)pyi + 0.5f;

    int h  = (listlen + 1) >> 1;
    int lo = half ? h : 0;
    int hi = half ? listlen : h;

    float bestz = 0.0f;
    int   besti = -1;

    #pragma unroll 2
    for (int k = lo; k < hi; k++) {
        float4 q0 = sm->s0[k];
        float4 q1 = sm->s1[k];
        float4 q2 = sm->s2[k];
        float4 q3 = sm->s3[k];
        float w0 = q0.x * (py - q0.w) - q0.y * (px - q0.z); // E(b,c)
        float w1 = q1.x * (py - q1.w) - q1.y * (px - q1.z); // E(c,a)
        float w2 = q2.x * (py - q2.w) - q2.y * (px - q2.z); // E(a,b)
        float b0 = w0 * q3.w;
        float b1 = w1 * q3.w;
        float b2 = w2 * q3.w;
        float z  = b0 * q3.x + b1 * q3.y + b2 * q3.z;        // NaN if invalid
        bool inside = (b0 >= 0.0f) & (b1 >= 0.0f) & (b2 >= 0.0f) &
                      (z >= -1.0f) & (z <= 1.0f);
        if (inside && (besti < 0 || z < bestz)) { bestz = z; besti = sm->slist[k]; }
    }

    // pack sortable key: (monotone depth << 32) | tri_index; empty = ~0
    unsigned long long key = ~0ull;
    if (besti >= 0) {
        unsigned int d = __float_as_uint(bestz);
        d = (d & 0x80000000u) ? ~d : (d | 0x80000000u);
        key = ((unsigned long long)d << 32) | (unsigned int)besti;
    }

    if (half == 1) sm->mergebuf[pix] = key;
    __syncthreads();

    // ---- phase 5: merge + shade (lower half threads)
    if (half == 0) {
        unsigned long long kb = sm->mergebuf[pix];
        if (kb < key) key = kb;

        float r, g, bl;
        if (key != ~0ull) {
            int t = (int)(unsigned int)(key & 0xffffffffu);
            int i0 = f[3 * t], i1 = f[3 * t + 1], i2 = f[3 * t + 2];
            float4 A = sm->svd[i0], Bv = sm->svd[i1], C = sm->svd[i2];
            float ax = A.x, ay = A.y, bx = Bv.x, by = Bv.y, cx = C.x, cy = C.y;
            float w0 = (cx - bx) * (py - by) - (cy - by) * (px - bx);
            float w1 = (ax - cx) * (py - cy) - (ay - cy) * (px - cx);
            float w2 = (bx - ax) * (py - ay) - (by - ay) * (px - ax);
            float area = (bx - ax) * (cy - ay) - (by - ay) * (cx - ax);
            bool areaok = fabsf(area) > EPSV;
            float inva = 1.0f / (areaok ? area : 1.0f);
            float b0 = w0 * inva;
            float b1 = w1 * inva;
            float b2 = w2 * inva;
            float g0 = b0 * A.w, g1 = b1 * Bv.w, g2 = b2 * C.w;
            float den = g0 + g1 + g2;
            den = (fabsf(den) > EPSV) ? den : 1.0f;
            r  = (g0 * vc[3 * i0 + 0] + g1 * vc[3 * i1 + 0] + g2 * vc[3 * i2 + 0]) / den;
            g  = (g0 * vc[3 * i0 + 1] + g1 * vc[3 * i1 + 1] + g2 * vc[3 * i2 + 1]) / den;
            bl = (g0 * vc[3 * i0 + 2] + g1 * vc[3 * i1 + 2] + g2 * vc[3 * i2 + 2]) / den;
        } else {
            r = bg[0]; g = bg[1]; bl = bg[2];
        }
        int p = pyi * WIDTH + pxi;
        out[3 * p + 0] = r;
        out[3 * p + 1] = g;
        out[3 * p + 2] = bl;
    }
}

// --------- launch -----------------------------------------------------------
extern "C" void kernel_launch(void* const* d_in, const int* in_sizes, int n_in,
                              void* d_out, int out_size)
{
    const float* v     = (const float*)d_in[0];
    const float* vc    = (const float*)d_in[1];
    const int*   f     = (const int*)  d_in[2];
    const float* bg    = (const float*)d_in[3];
    const float* camf  = (const float*)d_in[4];
    const float* camc  = (const float*)d_in[5];
    const float* camt  = (const float*)d_in[6];
    const float* camrt = (const float*)d_in[7];

    int B = out_size / (NPIX * 3);
    int V = in_sizes[1] / 3;
    int F = in_sizes[2] / 3;
    if (V > VCAP) V = VCAP;
    if (F > FCAP) F = FCAP;

    cudaFuncSetAttribute(render_kernel,
                         cudaFuncAttributeMaxDynamicSharedMemorySize,
                         (int)sizeof(Smem));

    for (int b = 0; b < B; b++) {
        render_kernel<<<NBLOCKS, NTHREADS, sizeof(Smem)>>>(
            v + (size_t)b * V * 3, vc, f, bg, camf, camc, camt, camrt,
            (float*)d_out + (size_t)b * NPIX * 3, V, F);
    }
}

// round 6
// speedup vs baseline: 1.9939x; 1.4046x over previous
#include <cuda_runtime.h>
#include <math.h>

#define WIDTH   128
#define HEIGHT  128
#define NPIX    (WIDTH * HEIGHT)
#define NEARP   0.1f
#define FARP    10.0f
#define EPSV    1e-8f

#define TILE_W   16
#define TILE_H   8
#define TILES_X  (WIDTH / TILE_W)                   // 8
#define NBLOCKS  ((WIDTH/TILE_W)*(HEIGHT/TILE_H))   // 128
#define NTHREADS 512
#define NWARPS   (NTHREADS / 32)                    // 16
#define PIXPB    (TILE_W * TILE_H)                  // 128
#define NSPLIT   (NTHREADS / PIXPB)                 // 4
#define VCAP     1024
#define FCAP     1024

struct Smem {
    float4 svd[VCAP];                 // x, y, z(NaN if invalid), 1/w
    float4 s0[FCAP];                  // e0x, e0y, bx, by
    float4 s1[FCAP];                  // e1x, e1y, cx, cy
    float4 s2[FCAP];                  // e2x, e2y, ax, ay
    float4 s3[FCAP];                  // za, zb, zc, inva
    int    slist[FCAP];
    unsigned long long mergebuf[NSPLIT - 1][PIXPB];
    float  sM[16];
    int    wtot[NWARPS];
    int    wbase[NWARPS];
    int    slen;
};

__device__ __forceinline__ float f_nan() { return __int_as_float(0x7fc00000); }

// --------- camera matrix (view @ proj) --------------------------------------
__device__ void compute_matrix(const float* camf, const float* camc,
                               const float* camt, const float* camrt,
                               float* M)
{
    float f   = 0.5f * (camf[0] + camf[1]);
    float ccx = camc[0], ccy = camc[1];
    float nf  = NEARP / f;
    float right = ((float)WIDTH - (ccx + 0.5f)) * nf;
    float left  = -(ccx + 0.5f) * nf;
    float top   = (ccy + 0.5f) * nf;
    float bot   = -((float)HEIGHT - ccy + 0.5f) * nf;
    float m[4][4];
    #pragma unroll
    for (int i = 0; i < 4; i++)
        #pragma unroll
        for (int j = 0; j < 4; j++) m[i][j] = 0.0f;
    m[0][0] = 2.0f * NEARP / (right - left); m[0][2] = (right + left) / (right - left);
    m[1][1] = 2.0f * NEARP / (top - bot);    m[1][2] = (top + bot) / (top - bot);
    m[2][2] = -(FARP + NEARP) / (FARP - NEARP);
    m[2][3] = -2.0f * FARP * NEARP / (FARP - NEARP);
    m[3][2] = -1.0f;
    float P[4][4];
    #pragma unroll
    for (int i = 0; i < 4; i++)
        #pragma unroll
        for (int j = 0; j < 4; j++) P[i][j] = m[j][i];

    float rx = camrt[0], ry = camrt[1], rz = camrt[2];
    float th = sqrtf(rx * rx + ry * ry + rz * rz + 1e-12f);
    float kx = rx / th, ky = ry / th, kz = rz / th;
    float s  = sinf(th);
    float cc = 1.0f - cosf(th);
    float K[3][3] = {{0.f, -kz, ky}, {kz, 0.f, -kx}, {-ky, kx, 0.f}};
    float K2[3][3];
    #pragma unroll
    for (int i = 0; i < 3; i++)
        #pragma unroll
        for (int j = 0; j < 3; j++) {
            float acc = 0.f;
            #pragma unroll
            for (int k = 0; k < 3; k++) acc += K[i][k] * K[k][j];
            K2[i][j] = acc;
        }
    float R[3][3];
    #pragma unroll
    for (int i = 0; i < 3; i++)
        #pragma unroll
        for (int j = 0; j < 3; j++)
            R[i][j] = (i == j ? 1.0f : 0.0f) + s * K[i][j] + cc * K2[i][j];

    float Vw[4][4];
    #pragma unroll
    for (int i = 0; i < 4; i++)
        #pragma unroll
        for (int j = 0; j < 4; j++) Vw[i][j] = 0.0f;
    #pragma unroll
    for (int i = 0; i < 3; i++)
        #pragma unroll
        for (int j = 0; j < 3; j++) Vw[i][j] = R[j][i];
    Vw[3][0] = camt[0]; Vw[3][1] = camt[1]; Vw[3][2] = camt[2];
    Vw[3][3] = 1.0f;

    #pragma unroll
    for (int i = 0; i < 4; i++)
        #pragma unroll
        for (int j = 0; j < 4; j++) {
            float acc = 0.f;
            #pragma unroll
            for (int k = 0; k < 4; k++) acc += Vw[i][k] * P[k][j];
            M[i * 4 + j] = acc;
        }
}

__device__ __forceinline__ float4 transform_vertex(const float* __restrict__ v,
                                                   int i, const float* __restrict__ M)
{
    float x = v[3 * i], y = v[3 * i + 1], z = v[3 * i + 2];
    float c0 = x * M[0] + y * M[4] + z * M[8]  + M[12];
    float c1 = x * M[1] + y * M[5] + z * M[9]  + M[13];
    float c2 = x * M[2] + y * M[6] + z * M[10] + M[14];
    float c3 = x * M[3] + y * M[7] + z * M[11] + M[15];
    bool valid = (c3 > EPSV);
    float ws = valid ? c3 : 1.0f;
    float nx = c0 / ws, ny = c1 / ws, nz = c2 / ws;
    float4 r;
    r.x = (nx * 0.5f + 0.5f) * (float)WIDTH;
    r.y = (0.5f - ny * 0.5f) * (float)HEIGHT;
    r.z = valid ? nz : f_nan();
    r.w = 1.0f / ws;
    return r;
}

// --------- the whole renderer in one kernel ---------------------------------
__global__ void __launch_bounds__(NTHREADS, 1)
render_kernel(const float* __restrict__ v,
              const float* __restrict__ vc,
              const int* __restrict__ f,
              const float* __restrict__ bg,
              const float* __restrict__ camf,
              const float* __restrict__ camc,
              const float* __restrict__ camt,
              const float* __restrict__ camrt,
              float* __restrict__ out,
              int V, int F)
{
    extern __shared__ char raw[];
    Smem* sm = (Smem*)raw;

    int tid  = threadIdx.x;
    int lane = tid & 31;
    int wid  = tid >> 5;

    if (tid == 0) compute_matrix(camf, camc, camt, camrt, sm->sM);
    __syncthreads();

    // ---- phase 1: vertices -> smem
    for (int i = tid; i < V; i += NTHREADS)
        sm->svd[i] = transform_vertex(v, i, sm->sM);
    __syncthreads();

    // ---- tile geometry
    int tile = blockIdx.x;
    int tx0 = (tile % TILES_X) * TILE_W;
    int ty0 = (tile / TILES_X) * TILE_H;
    float tileL = (float)tx0, tileR = (float)(tx0 + TILE_W);
    float tileT = (float)ty0, tileB = (float)(ty0 + TILE_H);
    float cxm = tileL + 0.5f * (float)TILE_W;
    float cym = tileT + 0.5f * (float)TILE_H;
    const float hw = 0.5f * (float)TILE_W;
    const float hh = 0.5f * (float)TILE_H;

    // ---- phase 2: ordered compaction (bbox + conservative edge cull)
    //      thread t owns tris [2t, 2t+2)
    int tbase = tid * 2;
    unsigned passbits = 0;
    int cnt = 0;
    #pragma unroll
    for (int j = 0; j < 2; j++) {
        int t = tbase + j;
        if (t < F) {
            int i0 = f[3 * t], i1 = f[3 * t + 1], i2 = f[3 * t + 2];
            float4 A = sm->svd[i0], B = sm->svd[i1], C = sm->svd[i2];
            float ax = A.x, ay = A.y, bx = B.x, by = B.y, cx = C.x, cy = C.y;
            float xmn = fminf(ax, fminf(bx, cx));
            float xmx = fmaxf(ax, fmaxf(bx, cx));
            float ymn = fminf(ay, fminf(by, cy));
            float ymx = fmaxf(ay, fmaxf(by, cy));
            // bbox reject (NaN coords -> all compares false -> kept; harmless)
            bool reject = (xmx < tileL) | (xmn > tileR) | (ymx < tileT) | (ymn > tileB);
            if (!reject) {
                // conservative half-plane cull: reject iff b_i < 0 provably
                // holds over the whole tile (linear bound + fp slack).
                float e0x = cx - bx, e0y = cy - by;
                float e1x = ax - cx, e1y = ay - cy;
                float e2x = bx - ax, e2y = by - ay;
                float area = e2x * (cy - ay) - e2y * (cx - ax);
                bool areaok = fabsf(area) > EPSV;
                float inva = 1.0f / (areaok ? area : 1.0f);
                float ai = fabsf(inva);
                float w0c = e0x * (cym - by) - e0y * (cxm - bx);
                float w1c = e1x * (cym - cy) - e1y * (cxm - cx);
                float w2c = e2x * (cym - ay) - e2y * (cxm - ax);
                float rb0 = (fabsf(e0y) * hw + fabsf(e0x) * hh) * ai * 1.001f + 1e-3f;
                float rb1 = (fabsf(e1y) * hw + fabsf(e1x) * hh) * ai * 1.001f + 1e-3f;
                float rb2 = (fabsf(e2y) * hw + fabsf(e2x) * hh) * ai * 1.001f + 1e-3f;
                float b0c = w0c * inva, b1c = w1c * inva, b2c = w2c * inva;
                // NaN -> compares false -> kept (safe)
                bool ereject = (b0c < -rb0) | (b1c < -rb1) | (b2c < -rb2);
                if (!ereject) { passbits |= (1u << j); cnt++; }
            }
        }
    }
    // block exclusive scan of cnt
    int x = cnt;
    #pragma unroll
    for (int o = 1; o < 32; o <<= 1) {
        int y = __shfl_up_sync(0xffffffffu, x, o);
        if (lane >= o) x += y;
    }
    if (lane == 31) sm->wtot[wid] = x;
    __syncthreads();
    if (tid == 0) {
        int s = 0;
        #pragma unroll
        for (int i = 0; i < NWARPS; i++) { sm->wbase[i] = s; s += sm->wtot[i]; }
        sm->slen = s;
    }
    __syncthreads();
    int o = sm->wbase[wid] + x - cnt;   // exclusive offset, order preserved
    #pragma unroll
    for (int j = 0; j < 2; j++)
        if (passbits & (1u << j)) sm->slist[o++] = tbase + j;
    __syncthreads();

    int listlen = sm->slen;

    // ---- phase 3: setup surviving triangles (same fp forms as always)
    for (int k = tid; k < listlen; k += NTHREADS) {
        int t = sm->slist[k];
        int i0 = f[3 * t], i1 = f[3 * t + 1], i2 = f[3 * t + 2];
        float4 A = sm->svd[i0], Bv = sm->svd[i1], C = sm->svd[i2];
        float ax = A.x, ay = A.y, bx = Bv.x, by = Bv.y, cx = C.x, cy = C.y;
        float e0x = cx - bx, e0y = cy - by;
        float e1x = ax - cx, e1y = ay - cy;
        float e2x = bx - ax, e2y = by - ay;
        float area = e2x * (cy - ay) - e2y * (cx - ax);
        bool areaok = fabsf(area) > EPSV;
        float inva = 1.0f / (areaok ? area : 1.0f);
        float za = A.z, zb = Bv.z, zc = C.z;   // NaN if vert invalid
        if (!areaok) za = f_nan();
        sm->s0[k] = make_float4(e0x, e0y, bx, by);
        sm->s1[k] = make_float4(e1x, e1y, cx, cy);
        sm->s2[k] = make_float4(e2x, e2y, ax, ay);
        sm->s3[k] = make_float4(za, zb, zc, inva);
    }
    __syncthreads();

    // ---- phase 4: raster. tid&127 = pixel, tid>>7 = list quarter.
    int pix = tid & (PIXPB - 1);
    int seg = tid >> 7;                     // 0..3
    int pxi = tx0 + (pix % TILE_W);
    int pyi = ty0 + (pix / TILE_W);
    float px = (float)pxi + 0.5f;
    float py = (float)pyi + 0.5f;

    int qlen = (listlen + NSPLIT - 1) / NSPLIT;
    int lo = seg * qlen;
    int hi = lo + qlen; if (hi > listlen) hi = listlen;

    float bestz = 0.0f;
    int   besti = -1;

    #pragma unroll 2
    for (int k = lo; k < hi; k++) {
        float4 q0 = sm->s0[k];
        float4 q1 = sm->s1[k];
        float4 q2 = sm->s2[k];
        float4 q3 = sm->s3[k];
        float w0 = q0.x * (py - q0.w) - q0.y * (px - q0.z); // E(b,c)
        float w1 = q1.x * (py - q1.w) - q1.y * (px - q1.z); // E(c,a)
        float w2 = q2.x * (py - q2.w) - q2.y * (px - q2.z); // E(a,b)
        float b0 = w0 * q3.w;
        float b1 = w1 * q3.w;
        float b2 = w2 * q3.w;
        float z  = b0 * q3.x + b1 * q3.y + b2 * q3.z;        // NaN if invalid
        bool inside = (b0 >= 0.0f) & (b1 >= 0.0f) & (b2 >= 0.0f) &
                      (z >= -1.0f) & (z <= 1.0f);
        if (inside && (besti < 0 || z < bestz)) { bestz = z; besti = sm->slist[k]; }
    }

    // pack sortable key: (monotone depth << 32) | tri_index; empty = ~0
    unsigned long long key = ~0ull;
    if (besti >= 0) {
        unsigned int d = __float_as_uint(bestz);
        d = (d & 0x80000000u) ? ~d : (d | 0x80000000u);
        key = ((unsigned long long)d << 32) | (unsigned int)besti;
    }

    if (seg > 0) sm->mergebuf[seg - 1][pix] = key;
    __syncthreads();

    // ---- phase 5: merge + shade (segment-0 threads)
    if (seg == 0) {
        #pragma unroll
        for (int s = 0; s < NSPLIT - 1; s++) {
            unsigned long long kb = sm->mergebuf[s][pix];
            if (kb < key) key = kb;
        }

        float r, g, bl;
        if (key != ~0ull) {
            int t = (int)(unsigned int)(key & 0xffffffffu);
            int i0 = f[3 * t], i1 = f[3 * t + 1], i2 = f[3 * t + 2];
            float4 A = sm->svd[i0], Bv = sm->svd[i1], C = sm->svd[i2];
            float ax = A.x, ay = A.y, bx = Bv.x, by = Bv.y, cx = C.x, cy = C.y;
            float w0 = (cx - bx) * (py - by) - (cy - by) * (px - bx);
            float w1 = (ax - cx) * (py - cy) - (ay - cy) * (px - cx);
            float w2 = (bx - ax) * (py - ay) - (by - ay) * (px - ax);
            float area = (bx - ax) * (cy - ay) - (by - ay) * (cx - ax);
            bool areaok = fabsf(area) > EPSV;
            float inva = 1.0f / (areaok ? area : 1.0f);
            float b0 = w0 * inva;
            float b1 = w1 * inva;
            float b2 = w2 * inva;
            float g0 = b0 * A.w, g1 = b1 * Bv.w, g2 = b2 * C.w;
            float den = g0 + g1 + g2;
            den = (fabsf(den) > EPSV) ? den : 1.0f;
            r  = (g0 * vc[3 * i0 + 0] + g1 * vc[3 * i1 + 0] + g2 * vc[3 * i2 + 0]) / den;
            g  = (g0 * vc[3 * i0 + 1] + g1 * vc[3 * i1 + 1] + g2 * vc[3 * i2 + 1]) / den;
            bl = (g0 * vc[3 * i0 + 2] + g1 * vc[3 * i1 + 2] + g2 * vc[3 * i2 + 2]) / den;
        } else {
            r = bg[0]; g = bg[1]; bl = bg[2];
        }
        int p = pyi * WIDTH + pxi;
        out[3 * p + 0] = r;
        out[3 * p + 1] = g;
        out[3 * p + 2] = bl;
    }
}

// --------- launch -----------------------------------------------------------
extern "C" void kernel_launch(void* const* d_in, const int* in_sizes, int n_in,
                              void* d_out, int out_size)
{
    const float* v     = (const float*)d_in[0];
    const float* vc    = (const float*)d_in[1];
    const int*   f     = (const int*)  d_in[2];
    const float* bg    = (const float*)d_in[3];
    const float* camf  = (const float*)d_in[4];
    const float* camc  = (const float*)d_in[5];
    const float* camt  = (const float*)d_in[6];
    const float* camrt = (const float*)d_in[7];

    int B = out_size / (NPIX * 3);
    int V = in_sizes[1] / 3;
    int F = in_sizes[2] / 3;
    if (V > VCAP) V = VCAP;
    if (F > FCAP) F = FCAP;

    cudaFuncSetAttribute(render_kernel,
                         cudaFuncAttributeMaxDynamicSharedMemorySize,
                         (int)sizeof(Smem));

    for (int b = 0; b < B; b++) {
        render_kernel<<<NBLOCKS, NTHREADS, sizeof(Smem)>>>(
            v + (size_t)b * V * 3, vc, f, bg, camf, camc, camt, camrt,
            (float*)d_out + (size_t)b * NPIX * 3, V, F);
    }
}

// round 8
// speedup vs baseline: 2.0092x; 1.0077x over previous
#include <cuda_runtime.h>
#include <math.h>

#define WIDTH   128
#define HEIGHT  128
#define NPIX    (WIDTH * HEIGHT)
#define NEARP   0.1f
#define FARP    10.0f
#define EPSV    1e-8f

#define TILE_W   16
#define TILE_H   8
#define TILES_X  (WIDTH / TILE_W)                   // 8
#define NBLOCKS  ((WIDTH/TILE_W)*(HEIGHT/TILE_H))   // 128
#define NTHREADS 1024
#define NWARPS   (NTHREADS / 32)                    // 32
#define PIXPB    (TILE_W * TILE_H)                  // 128
#define NSPLIT   (NTHREADS / PIXPB)                 // 8
#define VCAP     1024
#define FCAP     1024

struct Smem {
    float4 svd[VCAP];                 // x, y, z(NaN if invalid), 1/w
    float4 s0[FCAP];                  // e0x, e0y, bx, by
    float4 s1[FCAP];                  // e1x, e1y, cx, cy
    float4 s2[FCAP];                  // e2x, e2y, ax, ay
    float4 s3[FCAP];                  // za, zb, zc, inva
    int    slist[FCAP];
    unsigned long long mergebuf[NSPLIT - 1][PIXPB];
    float  sM[16];
    int    wtot[NWARPS];
    int    wbase[NWARPS];
    int    slen;
};

__device__ __forceinline__ float f_nan() { return __int_as_float(0x7fc00000); }

// --------- camera matrix (view @ proj) --------------------------------------
__device__ void compute_matrix(const float* camf, const float* camc,
                               const float* camt, const float* camrt,
                               float* M)
{
    float f   = 0.5f * (camf[0] + camf[1]);
    float ccx = camc[0], ccy = camc[1];
    float nf  = NEARP / f;
    float right = ((float)WIDTH - (ccx + 0.5f)) * nf;
    float left  = -(ccx + 0.5f) * nf;
    float top   = (ccy + 0.5f) * nf;
    float bot   = -((float)HEIGHT - ccy + 0.5f) * nf;
    float m[4][4];
    #pragma unroll
    for (int i = 0; i < 4; i++)
        #pragma unroll
        for (int j = 0; j < 4; j++) m[i][j] = 0.0f;
    m[0][0] = 2.0f * NEARP / (right - left); m[0][2] = (right + left) / (right - left);
    m[1][1] = 2.0f * NEARP / (top - bot);    m[1][2] = (top + bot) / (top - bot);
    m[2][2] = -(FARP + NEARP) / (FARP - NEARP);
    m[2][3] = -2.0f * FARP * NEARP / (FARP - NEARP);
    m[3][2] = -1.0f;
    float P[4][4];
    #pragma unroll
    for (int i = 0; i < 4; i++)
        #pragma unroll
        for (int j = 0; j < 4; j++) P[i][j] = m[j][i];

    float rx = camrt[0], ry = camrt[1], rz = camrt[2];
    float th = sqrtf(rx * rx + ry * ry + rz * rz + 1e-12f);
    float kx = rx / th, ky = ry / th, kz = rz / th;
    float s  = sinf(th);
    float cc = 1.0f - cosf(th);
    float K[3][3] = {{0.f, -kz, ky}, {kz, 0.f, -kx}, {-ky, kx, 0.f}};
    float K2[3][3];
    #pragma unroll
    for (int i = 0; i < 3; i++)
        #pragma unroll
        for (int j = 0; j < 3; j++) {
            float acc = 0.f;
            #pragma unroll
            for (int k = 0; k < 3; k++) acc += K[i][k] * K[k][j];
            K2[i][j] = acc;
        }
    float R[3][3];
    #pragma unroll
    for (int i = 0; i < 3; i++)
        #pragma unroll
        for (int j = 0; j < 3; j++)
            R[i][j] = (i == j ? 1.0f : 0.0f) + s * K[i][j] + cc * K2[i][j];

    float Vw[4][4];
    #pragma unroll
    for (int i = 0; i < 4; i++)
        #pragma unroll
        for (int j = 0; j < 4; j++) Vw[i][j] = 0.0f;
    #pragma unroll
    for (int i = 0; i < 3; i++)
        #pragma unroll
        for (int j = 0; j < 3; j++) Vw[i][j] = R[j][i];
    Vw[3][0] = camt[0]; Vw[3][1] = camt[1]; Vw[3][2] = camt[2];
    Vw[3][3] = 1.0f;

    #pragma unroll
    for (int i = 0; i < 4; i++)
        #pragma unroll
        for (int j = 0; j < 4; j++) {
            float acc = 0.f;
            #pragma unroll
            for (int k = 0; k < 4; k++) acc += Vw[i][k] * P[k][j];
            M[i * 4 + j] = acc;
        }
}

__device__ __forceinline__ float4 transform_vertex(const float* __restrict__ v,
                                                   int i, const float* __restrict__ M)
{
    float x = v[3 * i], y = v[3 * i + 1], z = v[3 * i + 2];
    float c0 = x * M[0] + y * M[4] + z * M[8]  + M[12];
    float c1 = x * M[1] + y * M[5] + z * M[9]  + M[13];
    float c2 = x * M[2] + y * M[6] + z * M[10] + M[14];
    float c3 = x * M[3] + y * M[7] + z * M[11] + M[15];
    bool valid = (c3 > EPSV);
    float ws = valid ? c3 : 1.0f;
    float nx = c0 / ws, ny = c1 / ws, nz = c2 / ws;
    float4 r;
    r.x = (nx * 0.5f + 0.5f) * (float)WIDTH;
    r.y = (0.5f - ny * 0.5f) * (float)HEIGHT;
    r.z = valid ? nz : f_nan();
    r.w = 1.0f / ws;
    return r;
}

// --------- the whole renderer in one kernel ---------------------------------
__global__ void __launch_bounds__(NTHREADS, 1)
render_kernel(const float* __restrict__ v,
              const float* __restrict__ vc,
              const int* __restrict__ f,
              const float* __restrict__ bg,
              const float* __restrict__ camf,
              const float* __restrict__ camc,
              const float* __restrict__ camt,
              const float* __restrict__ camrt,
              float* __restrict__ out,
              int V, int F)
{
    extern __shared__ char raw[];
    Smem* sm = (Smem*)raw;

    int tid  = threadIdx.x;
    int lane = tid & 31;
    int wid  = tid >> 5;

    if (tid == 0) compute_matrix(camf, camc, camt, camrt, sm->sM);
    __syncthreads();

    // ---- phase 1: vertices -> smem
    for (int i = tid; i < V; i += NTHREADS)
        sm->svd[i] = transform_vertex(v, i, sm->sM);
    __syncthreads();

    // ---- tile geometry
    int tile = blockIdx.x;
    int tx0 = (tile % TILES_X) * TILE_W;
    int ty0 = (tile / TILES_X) * TILE_H;
    float tileL = (float)tx0, tileR = (float)(tx0 + TILE_W);
    float tileT = (float)ty0, tileB = (float)(ty0 + TILE_H);
    float cxm = tileL + 0.5f * (float)TILE_W;
    float cym = tileT + 0.5f * (float)TILE_H;
    const float hw = 0.5f * (float)TILE_W;
    const float hh = 0.5f * (float)TILE_H;

    // ---- phase 2: ordered compaction (bbox + conservative edge cull)
    //      one triangle per thread
    int cnt = 0;
    {
        int t = tid;
        if (t < F) {
            int i0 = f[3 * t], i1 = f[3 * t + 1], i2 = f[3 * t + 2];
            float4 A = sm->svd[i0], B = sm->svd[i1], C = sm->svd[i2];
            float ax = A.x, ay = A.y, bx = B.x, by = B.y, cx = C.x, cy = C.y;
            float xmn = fminf(ax, fminf(bx, cx));
            float xmx = fmaxf(ax, fmaxf(bx, cx));
            float ymn = fminf(ay, fminf(by, cy));
            float ymx = fmaxf(ay, fmaxf(by, cy));
            // bbox reject (NaN coords -> all compares false -> kept; harmless)
            bool reject = (xmx < tileL) | (xmn > tileR) | (ymx < tileT) | (ymn > tileB);
            if (!reject) {
                // conservative half-plane cull: reject iff b_i < 0 provably
                // holds over the whole tile (linear bound + fp slack).
                float e0x = cx - bx, e0y = cy - by;
                float e1x = ax - cx, e1y = ay - cy;
                float e2x = bx - ax, e2y = by - ay;
                float area = e2x * (cy - ay) - e2y * (cx - ax);
                bool areaok = fabsf(area) > EPSV;
                float inva = 1.0f / (areaok ? area : 1.0f);
                float ai = fabsf(inva);
                float w0c = e0x * (cym - by) - e0y * (cxm - bx);
                float w1c = e1x * (cym - cy) - e1y * (cxm - cx);
                float w2c = e2x * (cym - ay) - e2y * (cxm - ax);
                float rb0 = (fabsf(e0y) * hw + fabsf(e0x) * hh) * ai * 1.001f + 1e-3f;
                float rb1 = (fabsf(e1y) * hw + fabsf(e1x) * hh) * ai * 1.001f + 1e-3f;
                float rb2 = (fabsf(e2y) * hw + fabsf(e2x) * hh) * ai * 1.001f + 1e-3f;
                float b0c = w0c * inva, b1c = w1c * inva, b2c = w2c * inva;
                // NaN -> compares false -> kept (safe)
                bool ereject = (b0c < -rb0) | (b1c < -rb1) | (b2c < -rb2);
                if (!ereject) cnt = 1;
            }
        }
    }
    // block exclusive scan of cnt
    int x = cnt;
    #pragma unroll
    for (int o = 1; o < 32; o <<= 1) {
        int y = __shfl_up_sync(0xffffffffu, x, o);
        if (lane >= o) x += y;
    }
    if (lane == 31) sm->wtot[wid] = x;
    __syncthreads();
    if (tid == 0) {
        int s = 0;
        #pragma unroll
        for (int i = 0; i < NWARPS; i++) { sm->wbase[i] = s; s += sm->wtot[i]; }
        sm->slen = s;
    }
    __syncthreads();
    if (cnt) sm->slist[sm->wbase[wid] + x - 1] = tid;  // order preserved
    __syncthreads();

    int listlen = sm->slen;

    // ---- phase 3: setup surviving triangles (same fp forms as always)
    for (int k = tid; k < listlen; k += NTHREADS) {
        int t = sm->slist[k];
        int i0 = f[3 * t], i1 = f[3 * t + 1], i2 = f[3 * t + 2];
        float4 A = sm->svd[i0], Bv = sm->svd[i1], C = sm->svd[i2];
        float ax = A.x, ay = A.y, bx = Bv.x, by = Bv.y, cx = C.x, cy = C.y;
        float e0x = cx - bx, e0y = cy - by;
        float e1x = ax - cx, e1y = ay - cy;
        float e2x = bx - ax, e2y = by - ay;
        float area = e2x * (cy - ay) - e2y * (cx - ax);
        bool areaok = fabsf(area) > EPSV;
        float inva = 1.0f / (areaok ? area : 1.0f);
        float za = A.z, zb = Bv.z, zc = C.z;   // NaN if vert invalid
        if (!areaok) za = f_nan();
        sm->s0[k] = make_float4(e0x, e0y, bx, by);
        sm->s1[k] = make_float4(e1x, e1y, cx, cy);
        sm->s2[k] = make_float4(e2x, e2y, ax, ay);
        sm->s3[k] = make_float4(za, zb, zc, inva);
    }
    __syncthreads();

    // ---- phase 4: raster. tid&127 = pixel, tid>>7 = list segment (0..7)
    int pix = tid & (PIXPB - 1);
    int seg = tid >> 7;
    int pxi = tx0 + (pix % TILE_W);
    int pyi = ty0 + (pix / TILE_W);
    float px = (float)pxi + 0.5f;
    float py = (float)pyi + 0.5f;

    int qlen = (listlen + NSPLIT - 1) / NSPLIT;
    int lo = seg * qlen;
    int hi = lo + qlen; if (hi > listlen) hi = listlen;

    float bestz = 0.0f;
    int   besti = -1;

    #pragma unroll 4
    for (int k = lo; k < hi; k++) {
        float4 q0 = sm->s0[k];
        float4 q1 = sm->s1[k];
        float4 q2 = sm->s2[k];
        float4 q3 = sm->s3[k];
        float w0 = q0.x * (py - q0.w) - q0.y * (px - q0.z); // E(b,c)
        float w1 = q1.x * (py - q1.w) - q1.y * (px - q1.z); // E(c,a)
        float w2 = q2.x * (py - q2.w) - q2.y * (px - q2.z); // E(a,b)
        float b0 = w0 * q3.w;
        float b1 = w1 * q3.w;
        float b2 = w2 * q3.w;
        float z  = b0 * q3.x + b1 * q3.y + b2 * q3.z;        // NaN if invalid
        bool inside = (b0 >= 0.0f) & (b1 >= 0.0f) & (b2 >= 0.0f) &
                      (z >= -1.0f) & (z <= 1.0f);
        if (inside && (besti < 0 || z < bestz)) { bestz = z; besti = sm->slist[k]; }
    }

    // pack sortable key: (monotone depth << 32) | tri_index; empty = ~0
    unsigned long long key = ~0ull;
    if (besti >= 0) {
        unsigned int d = __float_as_uint(bestz);
        d = (d & 0x80000000u) ? ~d : (d | 0x80000000u);
        key = ((unsigned long long)d << 32) | (unsigned int)besti;
    }

    if (seg > 0) sm->mergebuf[seg - 1][pix] = key;
    __syncthreads();

    // ---- phase 5: merge + shade (segment-0 threads)
    if (seg == 0) {
        #pragma unroll
        for (int s = 0; s < NSPLIT - 1; s++) {
            unsigned long long kb = sm->mergebuf[s][pix];
            if (kb < key) key = kb;
        }

        float r, g, bl;
        if (key != ~0ull) {
            int t = (int)(unsigned int)(key & 0xffffffffu);
            int i0 = f[3 * t], i1 = f[3 * t + 1], i2 = f[3 * t + 2];
            float4 A = sm->svd[i0], Bv = sm->svd[i1], C = sm->svd[i2];
            float ax = A.x, ay = A.y, bx = Bv.x, by = Bv.y, cx = C.x, cy = C.y;
            float w0 = (cx - bx) * (py - by) - (cy - by) * (px - bx);
            float w1 = (ax - cx) * (py - cy) - (ay - cy) * (px - cx);
            float w2 = (bx - ax) * (py - ay) - (by - ay) * (px - ax);
            float area = (bx - ax) * (cy - ay) - (by - ay) * (cx - ax);
            bool areaok = fabsf(area) > EPSV;
            float inva = 1.0f / (areaok ? area : 1.0f);
            float b0 = w0 * inva;
            float b1 = w1 * inva;
            float b2 = w2 * inva;
            float g0 = b0 * A.w, g1 = b1 * Bv.w, g2 = b2 * C.w;
            float den = g0 + g1 + g2;
            den = (fabsf(den) > EPSV) ? den : 1.0f;
            r  = (g0 * vc[3 * i0 + 0] + g1 * vc[3 * i1 + 0] + g2 * vc[3 * i2 + 0]) / den;
            g  = (g0 * vc[3 * i0 + 1] + g1 * vc[3 * i1 + 1] + g2 * vc[3 * i2 + 1]) / den;
            bl = (g0 * vc[3 * i0 + 2] + g1 * vc[3 * i1 + 2] + g2 * vc[3 * i2 + 2]) / den;
        } else {
            r = bg[0]; g = bg[1]; bl = bg[2];
        }
        int p = pyi * WIDTH + pxi;
        out[3 * p + 0] = r;
        out[3 * p + 1] = g;
        out[3 * p + 2] = bl;
    }
}

// --------- launch -----------------------------------------------------------
extern "C" void kernel_launch(void* const* d_in, const int* in_sizes, int n_in,
                              void* d_out, int out_size)
{
    const float* v     = (const float*)d_in[0];
    const float* vc    = (const float*)d_in[1];
    const int*   f     = (const int*)  d_in[2];
    const float* bg    = (const float*)d_in[3];
    const float* camf  = (const float*)d_in[4];
    const float* camc  = (const float*)d_in[5];
    const float* camt  = (const float*)d_in[6];
    const float* camrt = (const float*)d_in[7];

    int B = out_size / (NPIX * 3);
    int V = in_sizes[1] / 3;
    int F = in_sizes[2] / 3;
    if (V > VCAP) V = VCAP;
    if (F > FCAP) F = FCAP;

    cudaFuncSetAttribute(render_kernel,
                         cudaFuncAttributeMaxDynamicSharedMemorySize,
                         (int)sizeof(Smem));

    for (int b = 0; b < B; b++) {
        render_kernel<<<NBLOCKS, NTHREADS, sizeof(Smem)>>>(
            v + (size_t)b * V * 3, vc, f, bg, camf, camc, camt, camrt,
            (float*)d_out + (size_t)b * NPIX * 3, V, F);
    }
}

// round 10
// speedup vs baseline: 2.8207x; 1.4039x over previous
#include <cuda_runtime.h>
#include <math.h>

#define WIDTH   128
#define HEIGHT  128
#define NPIX    (WIDTH * HEIGHT)
#define NEARP   0.1f
#define FARP    10.0f
#define EPSV    1e-8f

#define TILE_W   8
#define TILE_H   8
#define TILES_X  (WIDTH / TILE_W)                   // 16
#define NBLOCKS  ((WIDTH/TILE_W)*(HEIGHT/TILE_H))   // 256
#define NTHREADS 512
#define NWARPS   (NTHREADS / 32)                    // 16
#define PIXPB    (TILE_W * TILE_H)                  // 64
#define NSPLIT   (NTHREADS / PIXPB)                 // 8
#define VCAP     1024
#define FCAP     1024

struct Smem {
    float4 svd[VCAP];                 // x, y, z(NaN if invalid), 1/w
    float4 s0[FCAP];                  // e0x, e0y, bx, by
    float4 s1[FCAP];                  // e1x, e1y, cx, cy
    float4 s2[FCAP];                  // e2x, e2y, ax, ay
    float4 s3[FCAP];                  // za, zb, zc, inva
    int    slist[FCAP];
    unsigned long long mergebuf[NSPLIT - 1][PIXPB];
    float  sM[16];
    int    wtot[NWARPS];
    int    wbase[NWARPS];
    int    slen;
};

__device__ __forceinline__ float f_nan() { return __int_as_float(0x7fc00000); }

// --------- camera matrix (view @ proj) --------------------------------------
__device__ void compute_matrix(const float* camf, const float* camc,
                               const float* camt, const float* camrt,
                               float* M)
{
    float f   = 0.5f * (camf[0] + camf[1]);
    float ccx = camc[0], ccy = camc[1];
    float nf  = NEARP / f;
    float right = ((float)WIDTH - (ccx + 0.5f)) * nf;
    float left  = -(ccx + 0.5f) * nf;
    float top   = (ccy + 0.5f) * nf;
    float bot   = -((float)HEIGHT - ccy + 0.5f) * nf;
    float m[4][4];
    #pragma unroll
    for (int i = 0; i < 4; i++)
        #pragma unroll
        for (int j = 0; j < 4; j++) m[i][j] = 0.0f;
    m[0][0] = 2.0f * NEARP / (right - left); m[0][2] = (right + left) / (right - left);
    m[1][1] = 2.0f * NEARP / (top - bot);    m[1][2] = (top + bot) / (top - bot);
    m[2][2] = -(FARP + NEARP) / (FARP - NEARP);
    m[2][3] = -2.0f * FARP * NEARP / (FARP - NEARP);
    m[3][2] = -1.0f;
    float P[4][4];
    #pragma unroll
    for (int i = 0; i < 4; i++)
        #pragma unroll
        for (int j = 0; j < 4; j++) P[i][j] = m[j][i];

    float rx = camrt[0], ry = camrt[1], rz = camrt[2];
    float th = sqrtf(rx * rx + ry * ry + rz * rz + 1e-12f);
    float kx = rx / th, ky = ry / th, kz = rz / th;
    float s  = sinf(th);
    float cc = 1.0f - cosf(th);
    float K[3][3] = {{0.f, -kz, ky}, {kz, 0.f, -kx}, {-ky, kx, 0.f}};
    float K2[3][3];
    #pragma unroll
    for (int i = 0; i < 3; i++)
        #pragma unroll
        for (int j = 0; j < 3; j++) {
            float acc = 0.f;
            #pragma unroll
            for (int k = 0; k < 3; k++) acc += K[i][k] * K[k][j];
            K2[i][j] = acc;
        }
    float R[3][3];
    #pragma unroll
    for (int i = 0; i < 3; i++)
        #pragma unroll
        for (int j = 0; j < 3; j++)
            R[i][j] = (i == j ? 1.0f : 0.0f) + s * K[i][j] + cc * K2[i][j];

    float Vw[4][4];
    #pragma unroll
    for (int i = 0; i < 4; i++)
        #pragma unroll
        for (int j = 0; j < 4; j++) Vw[i][j] = 0.0f;
    #pragma unroll
    for (int i = 0; i < 3; i++)
        #pragma unroll
        for (int j = 0; j < 3; j++) Vw[i][j] = R[j][i];
    Vw[3][0] = camt[0]; Vw[3][1] = camt[1]; Vw[3][2] = camt[2];
    Vw[3][3] = 1.0f;

    #pragma unroll
    for (int i = 0; i < 4; i++)
        #pragma unroll
        for (int j = 0; j < 4; j++) {
            float acc = 0.f;
            #pragma unroll
            for (int k = 0; k < 4; k++) acc += Vw[i][k] * P[k][j];
            M[i * 4 + j] = acc;
        }
}

__device__ __forceinline__ float4 transform_vertex(const float* __restrict__ v,
                                                   int i, const float* __restrict__ M)
{
    float x = v[3 * i], y = v[3 * i + 1], z = v[3 * i + 2];
    float c0 = x * M[0] + y * M[4] + z * M[8]  + M[12];
    float c1 = x * M[1] + y * M[5] + z * M[9]  + M[13];
    float c2 = x * M[2] + y * M[6] + z * M[10] + M[14];
    float c3 = x * M[3] + y * M[7] + z * M[11] + M[15];
    bool valid = (c3 > EPSV);
    float ws = valid ? c3 : 1.0f;
    float nx = c0 / ws, ny = c1 / ws, nz = c2 / ws;
    float4 r;
    r.x = (nx * 0.5f + 0.5f) * (float)WIDTH;
    r.y = (0.5f - ny * 0.5f) * (float)HEIGHT;
    r.z = valid ? nz : f_nan();
    r.w = 1.0f / ws;
    return r;
}

// --------- the whole renderer in one kernel ---------------------------------
__global__ void __launch_bounds__(NTHREADS, 2)
render_kernel(const float* __restrict__ v,
              const float* __restrict__ vc,
              const int* __restrict__ f,
              const float* __restrict__ bg,
              const float* __restrict__ camf,
              const float* __restrict__ camc,
              const float* __restrict__ camt,
              const float* __restrict__ camrt,
              float* __restrict__ out,
              int V, int F)
{
    extern __shared__ char raw[];
    Smem* sm = (Smem*)raw;

    int tid  = threadIdx.x;
    int lane = tid & 31;
    int wid  = tid >> 5;

    if (tid == 0) compute_matrix(camf, camc, camt, camrt, sm->sM);
    __syncthreads();

    // ---- phase 1: vertices -> smem
    for (int i = tid; i < V; i += NTHREADS)
        sm->svd[i] = transform_vertex(v, i, sm->sM);
    __syncthreads();

    // ---- tile geometry
    int tile = blockIdx.x;
    int tx0 = (tile % TILES_X) * TILE_W;
    int ty0 = (tile / TILES_X) * TILE_H;
    float tileL = (float)tx0, tileR = (float)(tx0 + TILE_W);
    float tileT = (float)ty0, tileB = (float)(ty0 + TILE_H);
    float cxm = tileL + 0.5f * (float)TILE_W;
    float cym = tileT + 0.5f * (float)TILE_H;
    const float hw = 0.5f * (float)TILE_W;
    const float hh = 0.5f * (float)TILE_H;

    // ---- phase 2: ordered compaction (bbox + conservative edge cull)
    //      thread t owns tris [2t, 2t+2)
    int tbase = tid * 2;
    unsigned passbits = 0;
    int cnt = 0;
    #pragma unroll
    for (int j = 0; j < 2; j++) {
        int t = tbase + j;
        if (t < F) {
            int i0 = f[3 * t], i1 = f[3 * t + 1], i2 = f[3 * t + 2];
            float4 A = sm->svd[i0], B = sm->svd[i1], C = sm->svd[i2];
            float ax = A.x, ay = A.y, bx = B.x, by = B.y, cx = C.x, cy = C.y;
            float xmn = fminf(ax, fminf(bx, cx));
            float xmx = fmaxf(ax, fmaxf(bx, cx));
            float ymn = fminf(ay, fminf(by, cy));
            float ymx = fmaxf(ay, fmaxf(by, cy));
            // bbox reject (NaN coords -> all compares false -> kept; harmless)
            bool reject = (xmx < tileL) | (xmn > tileR) | (ymx < tileT) | (ymn > tileB);
            if (!reject) {
                // conservative half-plane cull: reject iff b_i < 0 provably
                // holds over the whole tile (linear bound + fp slack).
                float e0x = cx - bx, e0y = cy - by;
                float e1x = ax - cx, e1y = ay - cy;
                float e2x = bx - ax, e2y = by - ay;
                float area = e2x * (cy - ay) - e2y * (cx - ax);
                bool areaok = fabsf(area) > EPSV;
                float inva = 1.0f / (areaok ? area : 1.0f);
                float ai = fabsf(inva);
                float w0c = e0x * (cym - by) - e0y * (cxm - bx);
                float w1c = e1x * (cym - cy) - e1y * (cxm - cx);
                float w2c = e2x * (cym - ay) - e2y * (cxm - ax);
                float rb0 = (fabsf(e0y) * hw + fabsf(e0x) * hh) * ai * 1.001f + 1e-3f;
                float rb1 = (fabsf(e1y) * hw + fabsf(e1x) * hh) * ai * 1.001f + 1e-3f;
                float rb2 = (fabsf(e2y) * hw + fabsf(e2x) * hh) * ai * 1.001f + 1e-3f;
                float b0c = w0c * inva, b1c = w1c * inva, b2c = w2c * inva;
                // NaN -> compares false -> kept (safe)
                bool ereject = (b0c < -rb0) | (b1c < -rb1) | (b2c < -rb2);
                if (!ereject) { passbits |= (1u << j); cnt++; }
            }
        }
    }
    // block exclusive scan of cnt
    int x = cnt;
    #pragma unroll
    for (int o = 1; o < 32; o <<= 1) {
        int y = __shfl_up_sync(0xffffffffu, x, o);
        if (lane >= o) x += y;
    }
    if (lane == 31) sm->wtot[wid] = x;
    __syncthreads();
    if (tid == 0) {
        int s = 0;
        #pragma unroll
        for (int i = 0; i < NWARPS; i++) { sm->wbase[i] = s; s += sm->wtot[i]; }
        sm->slen = s;
    }
    __syncthreads();
    int o = sm->wbase[wid] + x - cnt;   // exclusive offset, order preserved
    #pragma unroll
    for (int j = 0; j < 2; j++)
        if (passbits & (1u << j)) sm->slist[o++] = tbase + j;
    __syncthreads();

    int listlen = sm->slen;

    // ---- phase 3: setup surviving triangles (same fp forms as always)
    for (int k = tid; k < listlen; k += NTHREADS) {
        int t = sm->slist[k];
        int i0 = f[3 * t], i1 = f[3 * t + 1], i2 = f[3 * t + 2];
        float4 A = sm->svd[i0], Bv = sm->svd[i1], C = sm->svd[i2];
        float ax = A.x, ay = A.y, bx = Bv.x, by = Bv.y, cx = C.x, cy = C.y;
        float e0x = cx - bx, e0y = cy - by;
        float e1x = ax - cx, e1y = ay - cy;
        float e2x = bx - ax, e2y = by - ay;
        float area = e2x * (cy - ay) - e2y * (cx - ax);
        bool areaok = fabsf(area) > EPSV;
        float inva = 1.0f / (areaok ? area : 1.0f);
        float za = A.z, zb = Bv.z, zc = C.z;   // NaN if vert invalid
        if (!areaok) za = f_nan();
        sm->s0[k] = make_float4(e0x, e0y, bx, by);
        sm->s1[k] = make_float4(e1x, e1y, cx, cy);
        sm->s2[k] = make_float4(e2x, e2y, ax, ay);
        sm->s3[k] = make_float4(za, zb, zc, inva);
    }
    __syncthreads();

    // ---- phase 4: raster. tid&63 = pixel, tid>>6 = list segment (0..7)
    int pix = tid & (PIXPB - 1);
    int seg = tid >> 6;
    int pxi = tx0 + (pix % TILE_W);
    int pyi = ty0 + (pix / TILE_W);
    float px = (float)pxi + 0.5f;
    float py = (float)pyi + 0.5f;

    int qlen = (listlen + NSPLIT - 1) / NSPLIT;
    int lo = seg * qlen;
    int hi = lo + qlen; if (hi > listlen) hi = listlen;

    float bestz = 0.0f;
    int   bestk = -1;

    #pragma unroll 4
    for (int k = lo; k < hi; k++) {
        float4 q0 = sm->s0[k];
        float4 q1 = sm->s1[k];
        float4 q2 = sm->s2[k];
        float4 q3 = sm->s3[k];
        float w0 = q0.x * (py - q0.w) - q0.y * (px - q0.z); // E(b,c)
        float w1 = q1.x * (py - q1.w) - q1.y * (px - q1.z); // E(c,a)
        float w2 = q2.x * (py - q2.w) - q2.y * (px - q2.z); // E(a,b)
        float b0 = w0 * q3.w;
        float b1 = w1 * q3.w;
        float b2 = w2 * q3.w;
        float z  = b0 * q3.x + b1 * q3.y + b2 * q3.z;        // NaN if invalid
        bool inside = (b0 >= 0.0f) & (b1 >= 0.0f) & (b2 >= 0.0f) &
                      (z >= -1.0f) & (z <= 1.0f);
        if (inside && (bestk < 0 || z < bestz)) { bestz = z; bestk = k; }
    }

    // pack sortable key: (monotone depth << 32) | tri_index; empty = ~0
    // (slist ascending => lowest k == lowest tri index; argmin tie-break kept)
    unsigned long long key = ~0ull;
    if (bestk >= 0) {
        unsigned int d = __float_as_uint(bestz);
        d = (d & 0x80000000u) ? ~d : (d | 0x80000000u);
        key = ((unsigned long long)d << 32) | (unsigned int)sm->slist[bestk];
    }

    if (seg > 0) sm->mergebuf[seg - 1][pix] = key;
    __syncthreads();

    // ---- phase 5: merge + shade (segment-0 threads)
    if (seg == 0) {
        #pragma unroll
        for (int s = 0; s < NSPLIT - 1; s++) {
            unsigned long long kb = sm->mergebuf[s][pix];
            if (kb < key) key = kb;
        }

        float r, g, bl;
        if (key != ~0ull) {
            int t = (int)(unsigned int)(key & 0xffffffffu);
            int i0 = f[3 * t], i1 = f[3 * t + 1], i2 = f[3 * t + 2];
            float4 A = sm->svd[i0], Bv = sm->svd[i1], C = sm->svd[i2];
            float ax = A.x, ay = A.y, bx = Bv.x, by = Bv.y, cx = C.x, cy = C.y;
            float w0 = (cx - bx) * (py - by) - (cy - by) * (px - bx);
            float w1 = (ax - cx) * (py - cy) - (ay - cy) * (px - cx);
            float w2 = (bx - ax) * (py - ay) - (by - ay) * (px - ax);
            float area = (bx - ax) * (cy - ay) - (by - ay) * (cx - ax);
            bool areaok = fabsf(area) > EPSV;
            float inva = 1.0f / (areaok ? area : 1.0f);
            float b0 = w0 * inva;
            float b1 = w1 * inva;
            float b2 = w2 * inva;
            float g0 = b0 * A.w, g1 = b1 * Bv.w, g2 = b2 * C.w;
            float den = g0 + g1 + g2;
            den = (fabsf(den) > EPSV) ? den : 1.0f;
            r  = (g0 * vc[3 * i0 + 0] + g1 * vc[3 * i1 + 0] + g2 * vc[3 * i2 + 0]) / den;
            g  = (g0 * vc[3 * i0 + 1] + g1 * vc[3 * i1 + 1] + g2 * vc[3 * i2 + 1]) / den;
            bl = (g0 * vc[3 * i0 + 2] + g1 * vc[3 * i1 + 2] + g2 * vc[3 * i2 + 2]) / den;
        } else {
            r = bg[0]; g = bg[1]; bl = bg[2];
        }
        int p = pyi * WIDTH + pxi;
        out[3 * p + 0] = r;
        out[3 * p + 1] = g;
        out[3 * p + 2] = bl;
    }
}

// --------- launch -----------------------------------------------------------
extern "C" void kernel_launch(void* const* d_in, const int* in_sizes, int n_in,
                              void* d_out, int out_size)
{
    const float* v     = (const float*)d_in[0];
    const float* vc    = (const float*)d_in[1];
    const int*   f     = (const int*)  d_in[2];
    const float* bg    = (const float*)d_in[3];
    const float* camf  = (const float*)d_in[4];
    const float* camc  = (const float*)d_in[5];
    const float* camt  = (const float*)d_in[6];
    const float* camrt = (const float*)d_in[7];

    int B = out_size / (NPIX * 3);
    int V = in_sizes[1] / 3;
    int F = in_sizes[2] / 3;
    if (V > VCAP) V = VCAP;
    if (F > FCAP) F = FCAP;

    cudaFuncSetAttribute(render_kernel,
                         cudaFuncAttributeMaxDynamicSharedMemorySize,
                         (int)sizeof(Smem));

    for (int b = 0; b < B; b++) {
        render_kernel<<<NBLOCKS, NTHREADS, sizeof(Smem)>>>(
            v + (size_t)b * V * 3, vc, f, bg, camf, camc, camt, camrt,
            (float*)d_out + (size_t)b * NPIX * 3, V, F);
    }
}